// round 3
// baseline (speedup 1.0000x reference)
#include <cuda_runtime.h>

#define NN 100000
#define NE 1600000
#define FF 128
#define KCH 4
#define PCD 32
#define HID 128
#define SCB 1024
#define NBLK ((NN + SCB - 1) / SCB)   // 98

// ---------------- scratch (no allocs allowed) ----------------
__device__ float g_c[(size_t)NN * HID];     // 51.2 MB  c[n][k*32+q]
__device__ float g_p[(size_t)NN * 8];       // 3.2 MB   p[n][0..3]=col-half proj, [4..7]=row-half proj
__device__ float g_w[(size_t)NE * 4];       // 25.6 MB  softmax edge weights
__device__ float g_Weff[FF * HID];          // folded Wlin@Wconv
__device__ float g_beff[HID];               // folded blin@Wconv
__device__ int   g_deg[NN];
__device__ int   g_offs[NN];
__device__ int   g_rank[NE];
__device__ int   g_eid[NE];
__device__ int   g_ecl[NE];
__device__ int   g_bsums[128];

// ---------------- prep: Weff, beff ----------------
__global__ void k_prep(const float* __restrict__ Wlin,
                       const float* __restrict__ Wconv,
                       const float* __restrict__ blin) {
    int idx = blockIdx.x * blockDim.x + threadIdx.x;
    if (idx >= FF * HID) return;
    int f = idx >> 7, j = idx & 127;
    int k = j >> 5, q = j & 31;
    const float* wl = Wlin + ((size_t)k * FF + f) * PCD;
    const float* wc = Wconv + k * PCD * PCD + q;
    float s = 0.f;
#pragma unroll
    for (int p = 0; p < PCD; p++) s += wl[p] * wc[p * PCD];
    g_Weff[idx] = s;
    if (f == 0) {
        const float* bl = blin + k * PCD;
        float b = 0.f;
#pragma unroll
        for (int p = 0; p < PCD; p++) b += bl[p] * wc[p * PCD];
        g_beff[j] = b;
    }
}

__global__ void k_zero_deg() {
    int i = blockIdx.x * blockDim.x + threadIdx.x;
    if (i < NN) g_deg[i] = 0;
}

// ---------------- degree histogram (+rank) ----------------
__global__ void k_hist(const int* __restrict__ row) {
    int e = blockIdx.x * blockDim.x + threadIdx.x;
    if (e < NE) g_rank[e] = atomicAdd(&g_deg[row[e]], 1);
}

// ---------------- exclusive scan of deg -> offs ----------------
__global__ void k_scan1() {
    __shared__ int s[SCB];
    int b = blockIdx.x, t = threadIdx.x;
    int i = b * SCB + t;
    int v = (i < NN) ? g_deg[i] : 0;
    s[t] = v;
    __syncthreads();
    for (int d = 1; d < SCB; d <<= 1) {
        int tmp = (t >= d) ? s[t - d] : 0;
        __syncthreads();
        s[t] += tmp;
        __syncthreads();
    }
    if (i < NN) g_offs[i] = s[t] - v;
    if (t == SCB - 1) g_bsums[b] = s[t];
}

__global__ void k_scan2(int nb) {
    __shared__ int s[128];
    int t = threadIdx.x;
    s[t] = (t < nb) ? g_bsums[t] : 0;
    __syncthreads();
    if (t == 0) {
        int run = 0;
        for (int i = 0; i < nb; i++) { int v = s[i]; s[i] = run; run += v; }
    }
    __syncthreads();
    if (t < nb) g_bsums[t] = s[t];
}

__global__ void k_scan3() {
    int i = blockIdx.x * blockDim.x + threadIdx.x;
    if (i < NN) g_offs[i] += g_bsums[i >> 10];
}

// ---------------- scatter edges into CSR buckets ----------------
__global__ void k_scatter(const int* __restrict__ row, const int* __restrict__ col) {
    int e = blockIdx.x * blockDim.x + threadIdx.x;
    if (e >= NE) return;
    int r = row[e];
    int slot = g_offs[r] + g_rank[e];
    g_eid[slot] = e;
    g_ecl[slot] = col[e];
}

// ---------------- per-node projections for attention: p[N,8] ----------------
__global__ void k_proj(const float* __restrict__ x, const float* __restrict__ aW1) {
    int idx = blockIdx.x * blockDim.x + threadIdx.x;
    if (idx >= NN * 8) return;
    int n = idx >> 3, j = idx & 7;
    int k = j & 3;
    int off = (j >= 4) ? (FF * KCH) : 0;   // second half of aW1 rows (x[row] side)
    const float* xr = x + (size_t)n * FF;
    const float* w = aW1 + off + k;
    float s = 0.f;
#pragma unroll 8
    for (int f = 0; f < FF; f++) s += xr[f] * w[f * 4];
    g_p[idx] = s;
}

// ---------------- edge softmax weights ----------------
__global__ void k_edgew(const int* __restrict__ row, const int* __restrict__ col,
                        const float* __restrict__ ab1, const float* __restrict__ aW2,
                        const float* __restrict__ ab2) {
    int e = blockIdx.x * blockDim.x + threadIdx.x;
    if (e >= NE) return;
    int r = row[e], c = col[e];
    float4 pa = *(const float4*)(g_p + (size_t)c * 8);
    float4 pb = *(const float4*)(g_p + (size_t)r * 8 + 4);
    float h[4];
    h[0] = pa.x + pb.x + __ldg(&ab1[0]);
    h[1] = pa.y + pb.y + __ldg(&ab1[1]);
    h[2] = pa.z + pb.z + __ldg(&ab1[2]);
    h[3] = pa.w + pb.w + __ldg(&ab1[3]);
    float l[4];
#pragma unroll
    for (int j = 0; j < 4; j++) {
        float s = __ldg(&ab2[j]);
#pragma unroll
        for (int k = 0; k < 4; k++) s += h[k] * __ldg(&aW2[k * 4 + j]);
        l[j] = s;
    }
    float m = fmaxf(fmaxf(l[0], l[1]), fmaxf(l[2], l[3]));
    float e0 = expf(l[0] - m), e1 = expf(l[1] - m), e2 = expf(l[2] - m), e3 = expf(l[3] - m);
    float inv = 1.f / (e0 + e1 + e2 + e3);
    float4 w = make_float4(e0 * inv, e1 * inv, e2 * inv, e3 * inv);
    *(float4*)(g_w + (size_t)e * 4) = w;
}

// ---------------- GEMM: c = x @ Weff + beff  (128x128x16 tile, 256 thr, 8x8 micro) ----------------
__global__ void __launch_bounds__(256) k_gemm(const float* __restrict__ x) {
    __shared__ float As[16][128];
    __shared__ float Bs[16][128];
    int m0 = blockIdx.x * 128;
    int tid = threadIdx.x;
    int tx = tid & 15, ty = tid >> 4;
    float acc[8][8];
#pragma unroll
    for (int i = 0; i < 8; i++)
#pragma unroll
        for (int j = 0; j < 8; j++) acc[i][j] = 0.f;

    for (int f0 = 0; f0 < FF; f0 += 16) {
#pragma unroll
        for (int l = 0; l < 2; l++) {
            int li = tid + l * 256;          // 0..511
            int m = li >> 2;
            int k4 = (li & 3) << 2;
            float4 v = make_float4(0.f, 0.f, 0.f, 0.f);
            int gm = m0 + m;
            if (gm < NN) v = *(const float4*)(x + (size_t)gm * FF + f0 + k4);
            As[k4 + 0][m] = v.x; As[k4 + 1][m] = v.y;
            As[k4 + 2][m] = v.z; As[k4 + 3][m] = v.w;
        }
#pragma unroll
        for (int l = 0; l < 2; l++) {
            int li = tid + l * 256;
            int kk = li >> 5;
            int j4 = (li & 31) << 2;
            *(float4*)&Bs[kk][j4] = *(const float4*)(g_Weff + (f0 + kk) * HID + j4);
        }
        __syncthreads();
#pragma unroll
        for (int kk = 0; kk < 16; kk++) {
            float a[8], b[8];
            *(float4*)(a)     = *(float4*)&As[kk][ty * 8];
            *(float4*)(a + 4) = *(float4*)&As[kk][ty * 8 + 4];
            *(float4*)(b)     = *(float4*)&Bs[kk][tx * 8];
            *(float4*)(b + 4) = *(float4*)&Bs[kk][tx * 8 + 4];
#pragma unroll
            for (int i = 0; i < 8; i++)
#pragma unroll
                for (int j = 0; j < 8; j++) acc[i][j] += a[i] * b[j];
        }
        __syncthreads();
    }
#pragma unroll
    for (int i = 0; i < 8; i++) {
        int m = m0 + ty * 8 + i;
        if (m < NN) {
            float* cr = g_c + (size_t)m * HID + tx * 8;
#pragma unroll
            for (int j = 0; j < 8; j += 4) {
                float4 o;
                o.x = acc[i][j + 0] + g_beff[tx * 8 + j + 0];
                o.y = acc[i][j + 1] + g_beff[tx * 8 + j + 1];
                o.z = acc[i][j + 2] + g_beff[tx * 8 + j + 2];
                o.w = acc[i][j + 3] + g_beff[tx * 8 + j + 3];
                *(float4*)(cr + j) = o;
            }
        }
    }
}

// ---------------- aggregation + bias + L2 norm + classifier (warp per node) ----------------
__global__ void __launch_bounds__(256) k_agg(const float* __restrict__ bch,
                                             const float* __restrict__ Wcls,
                                             const float* __restrict__ bcls,
                                             float* __restrict__ outH,
                                             float* __restrict__ outL,
                                             int writeLogits) {
    int wid = (blockIdx.x * blockDim.x + threadIdx.x) >> 5;
    if (wid >= NN) return;
    int lane = threadIdx.x & 31;
    int k = lane >> 3;                        // channel owned by this lane's 4 cols
    int s = g_offs[wid];
    int eend = (wid == NN - 1) ? NE : g_offs[wid + 1];
    float4 acc = make_float4(0.f, 0.f, 0.f, 0.f);
    for (int j = s; j < eend; j++) {
        int e = g_eid[j];
        int cn = g_ecl[j];
        float wk = __ldg(&g_w[(size_t)e * 4 + k]);
        float4 cc = *(const float4*)(g_c + (size_t)cn * HID + lane * 4);
        acc.x += wk * cc.x; acc.y += wk * cc.y;
        acc.z += wk * cc.z; acc.w += wk * cc.w;
    }
    float4 b4 = ((const float4*)bch)[lane];
    acc.x += b4.x; acc.y += b4.y; acc.z += b4.z; acc.w += b4.w;
    float ss = acc.x * acc.x + acc.y * acc.y + acc.z * acc.z + acc.w * acc.w;
    ss += __shfl_xor_sync(0xffffffffu, ss, 1);
    ss += __shfl_xor_sync(0xffffffffu, ss, 2);
    ss += __shfl_xor_sync(0xffffffffu, ss, 4);
    float inv = 1.0f / fmaxf(sqrtf(ss), 1e-12f);
    acc.x *= inv; acc.y *= inv; acc.z *= inv; acc.w *= inv;
    ((float4*)(outH + (size_t)wid * HID))[lane] = acc;
    if (writeLogits) {
        float4 wc = ((const float4*)Wcls)[lane];
        float part = acc.x * wc.x + acc.y * wc.y + acc.z * wc.z + acc.w * wc.w;
#pragma unroll
        for (int o = 16; o; o >>= 1) part += __shfl_xor_sync(0xffffffffu, part, o);
        if (lane == 0) outL[wid] = part + __ldg(&bcls[0]);
    }
}

// ---------------- launch ----------------
extern "C" void kernel_launch(void* const* d_in, const int* in_sizes, int n_in,
                              void* d_out, int out_size) {
    const float* x    = (const float*)d_in[0];
    const int*   erow = (const int*)d_in[1];
    const int*   ecol = (const int*)d_in[2];
    const float* aW1  = (const float*)d_in[3];
    const float* ab1  = (const float*)d_in[4];
    const float* aW2  = (const float*)d_in[5];
    const float* ab2  = (const float*)d_in[6];
    const float* Wlin = (const float*)d_in[7];
    const float* blin = (const float*)d_in[8];
    const float* Wconv= (const float*)d_in[9];
    const float* bch  = (const float*)d_in[10];
    const float* Wcls = (const float*)d_in[11];
    const float* bcls = (const float*)d_in[12];
    float* out = (float*)d_out;

    k_prep<<<(FF * HID + 255) / 256, 256>>>(Wlin, Wconv, blin);
    k_zero_deg<<<(NN + 255) / 256, 256>>>();
    k_hist<<<(NE + 255) / 256, 256>>>(erow);
    k_gemm<<<(NN + 127) / 128, 256>>>(x);
    k_proj<<<(NN * 8 + 255) / 256, 256>>>(x, aW1);
    k_scan1<<<NBLK, SCB>>>();
    k_scan2<<<1, 128>>>(NBLK);
    k_scan3<<<(NN + 255) / 256, 256>>>();
    k_scatter<<<(NE + 255) / 256, 256>>>(erow, ecol);
    k_edgew<<<(NE + 255) / 256, 256>>>(erow, ecol, ab1, aW2, ab2);

    int writeLogits = (out_size >= NN * HID + NN) ? 1 : 0;
    k_agg<<<(NN * 32 + 255) / 256, 256>>>(bch, Wcls, bcls,
                                          out, out + (size_t)NN * HID, writeLogits);
}